// round 16
// baseline (speedup 1.0000x reference)
#include <cuda_runtime.h>
#include <cuda_fp16.h>
#include <cstdint>

#define ME   4096   // B*T rows
#define EMB  512
#define TT   2048
#define BB   2
#define HH   8
#define DD   64
#define WSZ  (EMB * EMB)

// ---- scratch (device globals; no cudaMalloc allowed) -----------------------
__device__ __align__(16) __half g_xh[ME * EMB];
__device__ __align__(16) __half g_wh[4 * WSZ];      // single fp16 weights
__device__ __align__(16) __half g_qh[ME * EMB];     // carries SC*log2e
__device__ __align__(16) __half g_kh[ME * EMB];     // carries SC
__device__ __align__(16) __half g_vh[ME * EMB];
__device__ __align__(16) __half g_oh[ME * EMB];

// ---- helpers ----------------------------------------------------------------
__device__ __forceinline__ unsigned sa(const void* p) {
    return (unsigned)__cvta_generic_to_shared(p);
}
__device__ __forceinline__ void ldsm4(unsigned r[4], unsigned addr) {
    asm volatile("ldmatrix.sync.aligned.m8n8.x4.shared.b16 {%0,%1,%2,%3}, [%4];"
                 : "=r"(r[0]), "=r"(r[1]), "=r"(r[2]), "=r"(r[3]) : "r"(addr));
}
__device__ __forceinline__ void ldsm4t(unsigned r[4], unsigned addr) {
    asm volatile("ldmatrix.sync.aligned.m8n8.x4.trans.shared.b16 {%0,%1,%2,%3}, [%4];"
                 : "=r"(r[0]), "=r"(r[1]), "=r"(r[2]), "=r"(r[3]) : "r"(addr));
}
__device__ __forceinline__ void mma16816h(float d[4], const unsigned a[4],
                                          unsigned b0, unsigned b1) {
    asm volatile(
        "mma.sync.aligned.m16n8k16.row.col.f32.f16.f16.f32 "
        "{%0,%1,%2,%3}, {%4,%5,%6,%7}, {%8,%9}, {%0,%1,%2,%3};"
        : "+f"(d[0]), "+f"(d[1]), "+f"(d[2]), "+f"(d[3])
        : "r"(a[0]), "r"(a[1]), "r"(a[2]), "r"(a[3]), "r"(b0), "r"(b1));
}
__device__ __forceinline__ unsigned pk2h(float lo, float hi) {    // f16x2
    __half2 t = __floats2half2_rn(lo, hi);
    return *reinterpret_cast<unsigned*>(&t);
}
__device__ __forceinline__ unsigned ex2h2(unsigned a) {           // 2^x on f16x2
    unsigned r;
    asm("ex2.approx.f16x2 %0, %1;" : "=r"(r) : "r"(a));
    return r;
}

#define CP_ASYNC16(dst, src) \
    asm volatile("cp.async.cg.shared.global [%0], [%1], 16;" :: "r"(dst), "l"(src))
#define CP_COMMIT() asm volatile("cp.async.commit_group;" ::: "memory")
#define CP_WAIT(n)  asm volatile("cp.async.wait_group %0;" :: "n"(n) : "memory")

// ---- fused convert: x and 4 weights -> fp16 ----------------------------------
__global__ void split_all(const float* __restrict__ x,
                          const float* __restrict__ w0, const float* __restrict__ w1,
                          const float* __restrict__ w2, const float* __restrict__ w3)
{
    int i = (blockIdx.x * blockDim.x + threadIdx.x) * 4;
    if (i < ME * EMB) {
        float4 v = *(const float4*)&x[i];
        *(__half2*)&g_xh[i]     = __floats2half2_rn(v.x, v.y);
        *(__half2*)&g_xh[i + 2] = __floats2half2_rn(v.z, v.w);
    } else {
        int j = i - ME * EMB;
        if (j >= 4 * WSZ) return;
        int z = j / WSZ, k = j % WSZ;
        const float* src = (z == 0) ? w0 : (z == 1) ? w1 : (z == 2) ? w2 : w3;
        float4 v = *(const float4*)&src[k];
        __half* dst = g_wh + (size_t)z * WSZ + k;
        *(__half2*)&dst[0] = __floats2half2_rn(v.x, v.y);
        *(__half2*)&dst[2] = __floats2half2_rn(v.z, v.w);
    }
}

// ---------------------------------------------------------------------------
// fp16 1-term GEMM body: C = A[M,512] @ W[N,512]^T (+bias).
// tile 256x64, 512 thr, 16 warps (8 Mrow x 2 Ncol), cp.async 3-stage pipeline
// with load-before-compute (one __syncthreads per k-tile). occ 1.
// smem/stage: A 36864 + W 9216 = 46080; 3 stages = 138240 B.
// ---------------------------------------------------------------------------
__device__ __forceinline__ void proj_body(
    const __half* __restrict__ Ah, const __half* __restrict__ Wh,
    const float* __restrict__ bias, float* __restrict__ C,
    __half* __restrict__ Hh,
    const float* __restrict__ gam, const float* __restrict__ bet, float lnsc)
{
    extern __shared__ __align__(16) char smp[];
    const unsigned smb = sa(smp);

    const int tid  = threadIdx.x;
    const int lane = tid & 31;
    const int w    = tid >> 5;      // 0..15
    const int wr   = w >> 1;        // 0..7  (32 rows each)
    const int wc   = w & 1;         // 0..1  (32 cols each)
    const int row0 = blockIdx.x * 256;
    const int col0 = blockIdx.y * 64;

    float acc[2][4][4];
#pragma unroll
    for (int m = 0; m < 2; m++)
#pragma unroll
        for (int j = 0; j < 4; j++)
#pragma unroll
            for (int e = 0; e < 4; e++) acc[m][j][e] = 0.f;

    auto load_stage = [&](int s, int kt) {
        const unsigned st = smb + (unsigned)s * 46080u;
        // A: 256 rows x 8 chunks = 2048 chunks, 512 thr -> 4 each
#pragma unroll
        for (int i = 0; i < 4; i++) {
            int idx = tid + i * 512;
            int r = idx >> 3, c = idx & 7;
            CP_ASYNC16(st + r * 144 + c * 16,
                       Ah + (size_t)(row0 + r) * EMB + kt * 64 + c * 8);
        }
        // W: 64 rows x 8 chunks = 512 chunks -> 1 each
        {
            int r = tid >> 3, c = tid & 7;
            CP_ASYNC16(st + 36864u + r * 144 + c * 16,
                       Wh + (size_t)(col0 + r) * EMB + kt * 64 + c * 8);
        }
    };

    const unsigned aoff = (wr * 32 + (lane & 15)) * 144 + (lane >> 4) * 16;
    const unsigned boff = 36864u +
        (wc * 32 + ((lane >> 4) << 3) + (lane & 7)) * 144 + (((lane >> 3) & 1) * 16);

    load_stage(0, 0); CP_COMMIT();
    load_stage(1, 1); CP_COMMIT();

    for (int kt = 0; kt < 8; kt++) {
        if (kt < 7) { CP_WAIT(1); } else { CP_WAIT(0); }
        __syncthreads();
        if (kt + 2 < 8) { load_stage((kt + 2) % 3, kt + 2); CP_COMMIT(); }
        const unsigned st = smb + (unsigned)(kt % 3) * 46080u;
        const unsigned aA = st + aoff;
        const unsigned aW = st + boff;
#pragma unroll
        for (int kc = 0; kc < 4; kc++) {
            unsigned a0[4], a1[4];
            ldsm4(a0, aA + kc * 32);
            ldsm4(a1, aA + kc * 32 + 16 * 144);
#pragma unroll
            for (int jp = 0; jp < 2; jp++) {
                unsigned bh[4];
                ldsm4(bh, aW + kc * 32 + jp * 16 * 144);
                mma16816h(acc[0][2 * jp],     a0, bh[0], bh[1]);
                mma16816h(acc[0][2 * jp + 1], a0, bh[2], bh[3]);
                mma16816h(acc[1][2 * jp],     a1, bh[0], bh[1]);
                mma16816h(acc[1][2 * jp + 1], a1, bh[2], bh[3]);
            }
        }
    }

    if (gam) {
        // ---- fused per-row LayerNorm + *lnsc -> fp16 -------------------------
        __syncthreads();
        float* redS = (float*)smp;          // [2][256]
        float* redQ = redS + 512;           // [2][256]
        float sum[2][2], ssq[2][2];
#pragma unroll
        for (int m = 0; m < 2; m++)
#pragma unroll
            for (int i = 0; i < 2; i++) {
                float s_ = 0.f, q_ = 0.f;
#pragma unroll
                for (int j = 0; j < 4; j++) {
                    float a0 = acc[m][j][2 * i], a1 = acc[m][j][2 * i + 1];
                    s_ += a0 + a1;
                    q_ += a0 * a0 + a1 * a1;
                }
                sum[m][i] = s_; ssq[m][i] = q_;
            }
#pragma unroll
        for (int off = 1; off <= 2; off <<= 1)
#pragma unroll
            for (int m = 0; m < 2; m++)
#pragma unroll
                for (int i = 0; i < 2; i++) {
                    sum[m][i] += __shfl_xor_sync(0xffffffffu, sum[m][i], off);
                    ssq[m][i] += __shfl_xor_sync(0xffffffffu, ssq[m][i], off);
                }
        if ((lane & 3) == 0) {
#pragma unroll
            for (int m = 0; m < 2; m++)
#pragma unroll
                for (int i = 0; i < 2; i++) {
                    int row = wr * 32 + m * 16 + i * 8 + (lane >> 2);
                    redS[wc * 256 + row] = sum[m][i];
                    redQ[wc * 256 + row] = ssq[m][i];
                }
        }
        __syncthreads();
#pragma unroll
        for (int m = 0; m < 2; m++)
#pragma unroll
            for (int i = 0; i < 2; i++) {
                const int row = wr * 32 + m * 16 + i * 8 + (lane >> 2);
                const float s_ = redS[row] + redS[256 + row];
                const float q_ = redQ[row] + redQ[256 + row];
                const float mean = s_ * (1.f / 64.f);
                const float var  = q_ * (1.f / 64.f) - mean * mean;
                const float rs   = rsqrtf(var + 1e-5f);
                const int gr = row0 + row;
#pragma unroll
                for (int j = 0; j < 4; j++) {
                    const int cl = wc * 32 + j * 8 + (lane & 3) * 2;
                    float v0 = ((acc[m][j][2 * i]     - mean) * rs * gam[cl]     + bet[cl])     * lnsc;
                    float v1 = ((acc[m][j][2 * i + 1] - mean) * rs * gam[cl + 1] + bet[cl + 1]) * lnsc;
                    *(unsigned*)&Hh[(size_t)gr * EMB + col0 + cl] = pk2h(v0, v1);
                }
            }
        return;
    }

    // ---- plain epilogue ------------------------------------------------------
#pragma unroll
    for (int m = 0; m < 2; m++) {
#pragma unroll
        for (int j = 0; j < 4; j++) {
            const int gr = row0 + wr * 32 + m * 16 + (lane >> 2);
            const int gc = col0 + wc * 32 + j * 8 + (lane & 3) * 2;
            float b0 = 0.f, b1 = 0.f;
            if (bias) { b0 = bias[gc]; b1 = bias[gc + 1]; }
            float v00 = acc[m][j][0] + b0, v01 = acc[m][j][1] + b1;
            float v10 = acc[m][j][2] + b0, v11 = acc[m][j][3] + b1;
            if (C) {
                *(float2*)&C[(size_t)gr * EMB + gc]       = make_float2(v00, v01);
                *(float2*)&C[(size_t)(gr + 8) * EMB + gc] = make_float2(v10, v11);
            }
            if (Hh) {
                *(unsigned*)&Hh[(size_t)gr * EMB + gc]       = pk2h(v00, v01);
                *(unsigned*)&Hh[(size_t)(gr + 8) * EMB + gc] = pk2h(v10, v11);
            }
        }
    }
}

__global__ __launch_bounds__(512, 1) void proj_qkv(
    const float* __restrict__ klng, const float* __restrict__ klnb,
    const float* __restrict__ qlng, const float* __restrict__ qlnb)
{
    const float SC  = 0.21022410381342865f;                        // 512^-0.25
    const float SCQ = 0.21022410381342865f * 1.4426950408889634f;  // * log2(e)
    const int z = blockIdx.z;
    const __half* Wh = g_wh + (size_t)z * WSZ;
    if (z == 0)
        proj_body(g_xh, Wh, nullptr, nullptr, g_kh, klng, klnb, SC);
    else if (z == 1)
        proj_body(g_xh, Wh, nullptr, nullptr, g_qh, qlng, qlnb, SCQ);
    else
        proj_body(g_xh, Wh, nullptr, nullptr, g_vh, nullptr, nullptr, 0.f);
}

__global__ __launch_bounds__(512, 1) void proj_out(const float* __restrict__ bias,
                                                   float* __restrict__ out)
{
    proj_body(g_oh, g_wh + 3 * (size_t)WSZ, bias, out, nullptr, nullptr, nullptr, 0.f);
}

// ---------------------------------------------------------------------------
// Flash attention (fp16, 1-term): 128-query tiles, 256 thr. Scores in log2
// domain (Q carries log2e); mask folded as additive -100 bias; softmax via
// ex2.approx.f16x2 (output IS the PV A-fragment); l in half2 per tile.
// 3-stage cp.async KV pipeline, load-before-compute, one sync per tile.
// smem: Q 18432 + 3 stages x {K,V} 18432 + mask 3x256 = 74496 B.  (R13 form)
// ---------------------------------------------------------------------------
__global__ __launch_bounds__(256, 2) void attn_mma(const float* __restrict__ mask)
{
    extern __shared__ __align__(16) char smraw[];
    const unsigned smb = sa(smraw);
    const unsigned QH = 0, KV = 18432u, MK = 73728u;

    const int b   = blockIdx.z;
    const int h   = blockIdx.y;
    const int t0  = blockIdx.x * 128;
    const int tid = threadIdx.x;
    const int lane = tid & 31;
    const int w    = tid >> 5;

    // ---- Q load (fp16), shares cp.async group 0 with KV stage 0 ----
#pragma unroll
    for (int i = 0; i < 4; i++) {
        int idx = tid + i * 256;
        int r = idx >> 3, c = idx & 7;
        size_t gi = (size_t)(b * TT + t0 + r) * EMB + h * DD + c * 8;
        CP_ASYNC16(smb + QH + r * 144 + c * 16, g_qh + gi);
    }

    auto load_kv = [&](int s, int kt) {
        const unsigned base = smb + KV + (unsigned)s * 18432u;
        const int s0 = kt * 64;
#pragma unroll
        for (int i = 0; i < 2; i++) {
            int idx = tid + i * 256;
            int r = idx >> 3, c = idx & 7;
            size_t gi = (size_t)(b * TT + s0 + r) * EMB + h * DD + c * 8;
            unsigned d = base + r * 144 + c * 16;
            CP_ASYNC16(d,         g_kh + gi);
            CP_ASYNC16(d + 9216u, g_vh + gi);
        }
        if (tid < 16)
            CP_ASYNC16(smb + MK + (unsigned)s * 256u + tid * 16,
                       mask + b * TT + s0 + tid * 4);
    };

    load_kv(0, 0); CP_COMMIT();
    load_kv(1, 1); CP_COMMIT();

    const unsigned qh_a = smb + QH + (w * 16 + (lane & 15)) * 144 + (lane >> 4) * 16;
    const unsigned koff = (((lane >> 4) << 3) + (lane & 7)) * 144 + ((lane >> 3) & 1) * 16;
    const unsigned voff = ((((lane >> 3) & 1) * 8 + (lane & 7)) * 72 + ((lane >> 4) << 3)) * 2;

    // ---- wait Q (+stage0), hoist Q fragments into registers ----
    CP_WAIT(1);
    __syncthreads();
    unsigned qhf[4][4];
#pragma unroll
    for (int kc = 0; kc < 4; kc++)
        ldsm4(qhf[kc], qh_a + kc * 32);

    float oa[8][4];
#pragma unroll
    for (int j = 0; j < 8; j++)
#pragma unroll
        for (int e = 0; e < 4; e++) oa[j][e] = 0.f;
    float l0 = 0.f, l1 = 0.f;

    const float rb0 = (mask[b * TT + t0 + w * 16 + (lane >> 2)]     > 0.f) ? 0.f : -100.f;
    const float rb1 = (mask[b * TT + t0 + w * 16 + (lane >> 2) + 8] > 0.f) ? 0.f : -100.f;

    for (int kt = 0; kt < TT / 64; kt++) {
        if (kt < TT / 64 - 1) { CP_WAIT(1); } else { CP_WAIT(0); }
        __syncthreads();
        if (kt + 2 < TT / 64) { load_kv((kt + 2) % 3, kt + 2); CP_COMMIT(); }

        const unsigned stb  = smb + KV + (unsigned)(kt % 3) * 18432u;
        const unsigned kh_a = stb + koff;
        const unsigned vh_a = stb + 9216u + voff;
        const float* mkbuf = (const float*)(smraw + MK + (unsigned)(kt % 3) * 256u);

        // ---- S (log2 domain) = Q * K ----
        float sc[8][4];
#pragma unroll
        for (int j = 0; j < 8; j++)
#pragma unroll
            for (int e = 0; e < 4; e++) sc[j][e] = 0.f;

#pragma unroll
        for (int kc = 0; kc < 4; kc++) {
#pragma unroll
            for (int jp = 0; jp < 4; jp++) {
                unsigned bh[4];
                ldsm4(bh, kh_a + kc * 32 + jp * 16 * 144);
                mma16816h(sc[2 * jp],     qhf[kc], bh[0], bh[1]);
                mma16816h(sc[2 * jp + 1], qhf[kc], bh[2], bh[3]);
            }
        }

        // ---- mask bias + packed ex2 -> P fragments; l in half2 ----
        unsigned p01[8], p23[8];
        __half2 lt0 = __floats2half2_rn(0.f, 0.f);
        __half2 lt1 = lt0;
#pragma unroll
        for (int j = 0; j < 8; j++) {
            int col = j * 8 + (lane & 3) * 2;
            float cb0 = (mkbuf[col]     > 0.f) ? 0.f : -100.f;
            float cb1 = (mkbuf[col + 1] > 0.f) ? 0.f : -100.f;
            p01[j] = ex2h2(pk2h(sc[j][0] + rb0 + cb0, sc[j][1] + rb0 + cb1));
            p23[j] = ex2h2(pk2h(sc[j][2] + rb1 + cb0, sc[j][3] + rb1 + cb1));
            lt0 = __hadd2(lt0, *reinterpret_cast<__half2*>(&p01[j]));
            lt1 = __hadd2(lt1, *reinterpret_cast<__half2*>(&p23[j]));
        }
        {
            float2 f0 = __half22float2(lt0);
            float2 f1 = __half22float2(lt1);
            l0 += f0.x + f0.y;
            l1 += f1.x + f1.y;
        }

        // ---- O += P * V ----
#pragma unroll
        for (int kc = 0; kc < 4; kc++) {
            unsigned a[4];
            a[0] = p01[2 * kc];     a[1] = p23[2 * kc];
            a[2] = p01[2 * kc + 1]; a[3] = p23[2 * kc + 1];
#pragma unroll
            for (int jp = 0; jp < 4; jp++) {
                unsigned bv[4];
                ldsm4t(bv, vh_a + kc * 16 * 144 + jp * 32);
                mma16816h(oa[2 * jp],     a, bv[0], bv[1]);
                mma16816h(oa[2 * jp + 1], a, bv[2], bv[3]);
            }
        }
    }

    // ---- epilogue: reduce l across quad, O / l -> fp16 ----
    l0 += __shfl_xor_sync(0xffffffffu, l0, 1);
    l0 += __shfl_xor_sync(0xffffffffu, l0, 2);
    l1 += __shfl_xor_sync(0xffffffffu, l1, 1);
    l1 += __shfl_xor_sync(0xffffffffu, l1, 2);
    const float inv0 = 1.f / l0;
    const float inv1 = 1.f / l1;
    const int gr0 = b * TT + t0 + w * 16 + (lane >> 2);
#pragma unroll
    for (int j = 0; j < 8; j++) {
        const int col = h * DD + j * 8 + (lane & 3) * 2;
        *(unsigned*)&g_oh[(size_t)gr0 * EMB + col] =
            pk2h(oa[j][0] * inv0, oa[j][1] * inv0);
        *(unsigned*)&g_oh[(size_t)(gr0 + 8) * EMB + col] =
            pk2h(oa[j][2] * inv1, oa[j][3] * inv1);
    }
}

// ---------------------------------------------------------------------------
extern "C" void kernel_launch(void* const* d_in, const int* in_sizes, int n_in,
                              void* d_out, int out_size)
{
    const float* x    = (const float*)d_in[0];
    const float* mask = (const float*)d_in[1];
    const float* Wk   = (const float*)d_in[2];
    const float* Wq   = (const float*)d_in[3];
    const float* Wv   = (const float*)d_in[4];
    const float* Wu   = (const float*)d_in[5];
    const float* bu   = (const float*)d_in[6];
    const float* klng = (const float*)d_in[7];
    const float* klnb = (const float*)d_in[8];
    const float* qlng = (const float*)d_in[9];
    const float* qlnb = (const float*)d_in[10];
    float* out = (float*)d_out;

    const int SPLIT_ITEMS = (ME * EMB + 4 * WSZ) / 4;
    split_all<<<(SPLIT_ITEMS + 255) / 256, 256>>>(x, Wk, Wq, Wv, Wu);

    const int PSMEM = 3 * 46080;  // 138240
    cudaFuncSetAttribute(proj_qkv,
                         cudaFuncAttributeMaxDynamicSharedMemorySize, PSMEM);
    cudaFuncSetAttribute(proj_out,
                         cudaFuncAttributeMaxDynamicSharedMemorySize, PSMEM);
    proj_qkv<<<dim3(ME / 256, EMB / 64, 3), 512, PSMEM>>>(klng, klnb, qlng, qlnb);

    const int ASMEM = 18432 + 3 * 18432 + 3 * 256;  // 74496
    cudaFuncSetAttribute(attn_mma,
                         cudaFuncAttributeMaxDynamicSharedMemorySize, ASMEM);
    attn_mma<<<dim3(TT / 128, HH, BB), 256, ASMEM>>>(mask);

    proj_out<<<dim3(ME / 256, EMB / 64, 1), 512, PSMEM>>>(bu, out);
}

// round 17
// speedup vs baseline: 1.0433x; 1.0433x over previous
#include <cuda_runtime.h>
#include <cuda_fp16.h>
#include <cstdint>

#define ME   4096   // B*T rows
#define EMB  512
#define TT   2048
#define BB   2
#define HH   8
#define DD   64
#define WSZ  (EMB * EMB)

// ---- scratch (device globals; no cudaMalloc allowed) -----------------------
__device__ __align__(16) __half g_xh[ME * EMB];
__device__ __align__(16) __half g_wh[4 * WSZ];      // single fp16 weights
__device__ __align__(16) __half g_qh[ME * EMB];     // carries SC*log2e
__device__ __align__(16) __half g_kh[ME * EMB];     // carries SC
__device__ __align__(16) __half g_vh[ME * EMB];
__device__ __align__(16) __half g_oh[ME * EMB];
__device__ __align__(16) __half g_mb[BB * TT];      // mask bias: 0 or -100 (fp16)

// ---- helpers ----------------------------------------------------------------
__device__ __forceinline__ unsigned sa(const void* p) {
    return (unsigned)__cvta_generic_to_shared(p);
}
__device__ __forceinline__ void ldsm4(unsigned r[4], unsigned addr) {
    asm volatile("ldmatrix.sync.aligned.m8n8.x4.shared.b16 {%0,%1,%2,%3}, [%4];"
                 : "=r"(r[0]), "=r"(r[1]), "=r"(r[2]), "=r"(r[3]) : "r"(addr));
}
__device__ __forceinline__ void ldsm4t(unsigned r[4], unsigned addr) {
    asm volatile("ldmatrix.sync.aligned.m8n8.x4.trans.shared.b16 {%0,%1,%2,%3}, [%4];"
                 : "=r"(r[0]), "=r"(r[1]), "=r"(r[2]), "=r"(r[3]) : "r"(addr));
}
__device__ __forceinline__ void mma16816h(float d[4], const unsigned a[4],
                                          unsigned b0, unsigned b1) {
    asm volatile(
        "mma.sync.aligned.m16n8k16.row.col.f32.f16.f16.f32 "
        "{%0,%1,%2,%3}, {%4,%5,%6,%7}, {%8,%9}, {%0,%1,%2,%3};"
        : "+f"(d[0]), "+f"(d[1]), "+f"(d[2]), "+f"(d[3])
        : "r"(a[0]), "r"(a[1]), "r"(a[2]), "r"(a[3]), "r"(b0), "r"(b1));
}
__device__ __forceinline__ unsigned pk2h(float lo, float hi) {    // f16x2
    __half2 t = __floats2half2_rn(lo, hi);
    return *reinterpret_cast<unsigned*>(&t);
}
__device__ __forceinline__ unsigned ex2h2(unsigned a) {           // 2^x on f16x2
    unsigned r;
    asm("ex2.approx.f16x2 %0, %1;" : "=r"(r) : "r"(a));
    return r;
}
__device__ __forceinline__ unsigned hadd2u(unsigned a, unsigned b) {
    unsigned r;
    asm("add.f16x2 %0, %1, %2;" : "=r"(r) : "r"(a), "r"(b));
    return r;
}

#define CP_ASYNC16(dst, src) \
    asm volatile("cp.async.cg.shared.global [%0], [%1], 16;" :: "r"(dst), "l"(src))
#define CP_COMMIT() asm volatile("cp.async.commit_group;" ::: "memory")
#define CP_WAIT(n)  asm volatile("cp.async.wait_group %0;" :: "n"(n) : "memory")

// ---- fused convert: x, 4 weights -> fp16; mask -> fp16 bias -------------------
__global__ void split_all(const float* __restrict__ x,
                          const float* __restrict__ w0, const float* __restrict__ w1,
                          const float* __restrict__ w2, const float* __restrict__ w3,
                          const float* __restrict__ mask)
{
    int i = (blockIdx.x * blockDim.x + threadIdx.x) * 4;
    if (i < ME * EMB) {
        float4 v = *(const float4*)&x[i];
        *(__half2*)&g_xh[i]     = __floats2half2_rn(v.x, v.y);
        *(__half2*)&g_xh[i + 2] = __floats2half2_rn(v.z, v.w);
    } else if (i < ME * EMB + 4 * WSZ) {
        int j = i - ME * EMB;
        int z = j / WSZ, k = j % WSZ;
        const float* src = (z == 0) ? w0 : (z == 1) ? w1 : (z == 2) ? w2 : w3;
        float4 v = *(const float4*)&src[k];
        __half* dst = g_wh + (size_t)z * WSZ + k;
        *(__half2*)&dst[0] = __floats2half2_rn(v.x, v.y);
        *(__half2*)&dst[2] = __floats2half2_rn(v.z, v.w);
    } else {
        int m = i - ME * EMB - 4 * WSZ;
        if (m >= BB * TT) return;
        float4 v = *(const float4*)&mask[m];
        *(__half2*)&g_mb[m] =
            __floats2half2_rn(v.x > 0.f ? 0.f : -100.f, v.y > 0.f ? 0.f : -100.f);
        *(__half2*)&g_mb[m + 2] =
            __floats2half2_rn(v.z > 0.f ? 0.f : -100.f, v.w > 0.f ? 0.f : -100.f);
    }
}

// ---------------------------------------------------------------------------
// fp16 1-term GEMM body: C = A[M,512] @ W[N,512]^T (+bias).
// tile 128x64, 256 thr, 8 warps (4 Mrow x 2 Ncol), cp.async 3-stage pipeline
// with load-before-compute (one __syncthreads per k-tile).   (R13 form)
// ---------------------------------------------------------------------------
__device__ __forceinline__ void proj_body(
    const __half* __restrict__ Ah, const __half* __restrict__ Wh,
    const float* __restrict__ bias, float* __restrict__ C,
    __half* __restrict__ Hh,
    const float* __restrict__ gam, const float* __restrict__ bet, float lnsc)
{
    extern __shared__ __align__(16) char smp[];
    const unsigned smb = sa(smp);

    const int tid  = threadIdx.x;
    const int lane = tid & 31;
    const int w    = tid >> 5;
    const int wr   = w & 3;
    const int wc   = w >> 2;
    const int row0 = blockIdx.x * 128;
    const int col0 = blockIdx.y * 64;

    const int lr  = tid >> 3;
    const int lcb = (tid & 7) * 16;
    const int lce = (tid & 7) * 8;

    float acc[2][4][4];
#pragma unroll
    for (int m = 0; m < 2; m++)
#pragma unroll
        for (int j = 0; j < 4; j++)
#pragma unroll
            for (int e = 0; e < 4; e++) acc[m][j][e] = 0.f;

    auto load_stage = [&](int s, int kt) {
        const unsigned st = smb + (unsigned)s * 27648u;
#pragma unroll
        for (int i = 0; i < 4; i++) {
            int r = lr + i * 32;
            CP_ASYNC16(st + r * 144 + lcb,
                       Ah + (size_t)(row0 + r) * EMB + kt * 64 + lce);
        }
#pragma unroll
        for (int i = 0; i < 2; i++) {
            int r = lr + i * 32;
            CP_ASYNC16(st + 18432u + r * 144 + lcb,
                       Wh + (size_t)(col0 + r) * EMB + kt * 64 + lce);
        }
    };

    const unsigned aoff = (wr * 32 + (lane & 15)) * 144 + (lane >> 4) * 16;
    const unsigned boff = 18432u +
        (wc * 32 + ((lane >> 4) << 3) + (lane & 7)) * 144 + (((lane >> 3) & 1) * 16);

    load_stage(0, 0); CP_COMMIT();
    load_stage(1, 1); CP_COMMIT();

    for (int kt = 0; kt < 8; kt++) {
        if (kt < 7) { CP_WAIT(1); } else { CP_WAIT(0); }
        __syncthreads();
        if (kt + 2 < 8) { load_stage((kt + 2) % 3, kt + 2); CP_COMMIT(); }
        const unsigned st = smb + (unsigned)(kt % 3) * 27648u;
        const unsigned aA = st + aoff;
        const unsigned aW = st + boff;
#pragma unroll
        for (int kc = 0; kc < 4; kc++) {
            unsigned a0[4], a1[4];
            ldsm4(a0, aA + kc * 32);
            ldsm4(a1, aA + kc * 32 + 16 * 144);
#pragma unroll
            for (int jp = 0; jp < 2; jp++) {
                unsigned bh[4];
                ldsm4(bh, aW + kc * 32 + jp * 16 * 144);
                mma16816h(acc[0][2 * jp],     a0, bh[0], bh[1]);
                mma16816h(acc[0][2 * jp + 1], a0, bh[2], bh[3]);
                mma16816h(acc[1][2 * jp],     a1, bh[0], bh[1]);
                mma16816h(acc[1][2 * jp + 1], a1, bh[2], bh[3]);
            }
        }
    }

    if (gam) {
        // ---- fused per-row LayerNorm + *lnsc -> fp16 -------------------------
        __syncthreads();
        float* redS = (float*)smp;          // [2][128]
        float* redQ = redS + 256;           // [2][128]
        float sum[2][2], ssq[2][2];
#pragma unroll
        for (int m = 0; m < 2; m++)
#pragma unroll
            for (int i = 0; i < 2; i++) {
                float s_ = 0.f, q_ = 0.f;
#pragma unroll
                for (int j = 0; j < 4; j++) {
                    float a0 = acc[m][j][2 * i], a1 = acc[m][j][2 * i + 1];
                    s_ += a0 + a1;
                    q_ += a0 * a0 + a1 * a1;
                }
                sum[m][i] = s_; ssq[m][i] = q_;
            }
#pragma unroll
        for (int off = 1; off <= 2; off <<= 1)
#pragma unroll
            for (int m = 0; m < 2; m++)
#pragma unroll
                for (int i = 0; i < 2; i++) {
                    sum[m][i] += __shfl_xor_sync(0xffffffffu, sum[m][i], off);
                    ssq[m][i] += __shfl_xor_sync(0xffffffffu, ssq[m][i], off);
                }
        if ((lane & 3) == 0) {
#pragma unroll
            for (int m = 0; m < 2; m++)
#pragma unroll
                for (int i = 0; i < 2; i++) {
                    int row = wr * 32 + m * 16 + i * 8 + (lane >> 2);
                    redS[wc * 128 + row] = sum[m][i];
                    redQ[wc * 128 + row] = ssq[m][i];
                }
        }
        __syncthreads();
#pragma unroll
        for (int m = 0; m < 2; m++)
#pragma unroll
            for (int i = 0; i < 2; i++) {
                const int row = wr * 32 + m * 16 + i * 8 + (lane >> 2);
                const float s_ = redS[row] + redS[128 + row];
                const float q_ = redQ[row] + redQ[128 + row];
                const float mean = s_ * (1.f / 64.f);
                const float var  = q_ * (1.f / 64.f) - mean * mean;
                const float rs   = rsqrtf(var + 1e-5f);
                const int gr = row0 + row;
#pragma unroll
                for (int j = 0; j < 4; j++) {
                    const int cl = wc * 32 + j * 8 + (lane & 3) * 2;
                    float v0 = ((acc[m][j][2 * i]     - mean) * rs * gam[cl]     + bet[cl])     * lnsc;
                    float v1 = ((acc[m][j][2 * i + 1] - mean) * rs * gam[cl + 1] + bet[cl + 1]) * lnsc;
                    *(unsigned*)&Hh[(size_t)gr * EMB + col0 + cl] = pk2h(v0, v1);
                }
            }
        return;
    }

    // ---- plain epilogue ------------------------------------------------------
#pragma unroll
    for (int m = 0; m < 2; m++) {
#pragma unroll
        for (int j = 0; j < 4; j++) {
            const int gr = row0 + wr * 32 + m * 16 + (lane >> 2);
            const int gc = col0 + wc * 32 + j * 8 + (lane & 3) * 2;
            float b0 = 0.f, b1 = 0.f;
            if (bias) { b0 = bias[gc]; b1 = bias[gc + 1]; }
            float v00 = acc[m][j][0] + b0, v01 = acc[m][j][1] + b1;
            float v10 = acc[m][j][2] + b0, v11 = acc[m][j][3] + b1;
            if (C) {
                *(float2*)&C[(size_t)gr * EMB + gc]       = make_float2(v00, v01);
                *(float2*)&C[(size_t)(gr + 8) * EMB + gc] = make_float2(v10, v11);
            }
            if (Hh) {
                *(unsigned*)&Hh[(size_t)gr * EMB + gc]       = pk2h(v00, v01);
                *(unsigned*)&Hh[(size_t)(gr + 8) * EMB + gc] = pk2h(v10, v11);
            }
        }
    }
}

__global__ __launch_bounds__(256, 2) void proj_qkv(
    const float* __restrict__ klng, const float* __restrict__ klnb,
    const float* __restrict__ qlng, const float* __restrict__ qlnb)
{
    const float SC  = 0.21022410381342865f;                        // 512^-0.25
    const float SCQ = 0.21022410381342865f * 1.4426950408889634f;  // * log2(e)
    const int z = blockIdx.z;
    const __half* Wh = g_wh + (size_t)z * WSZ;
    if (z == 0)
        proj_body(g_xh, Wh, nullptr, nullptr, g_kh, klng, klnb, SC);
    else if (z == 1)
        proj_body(g_xh, Wh, nullptr, nullptr, g_qh, qlng, qlnb, SCQ);
    else
        proj_body(g_xh, Wh, nullptr, nullptr, g_vh, nullptr, nullptr, 0.f);
}

__global__ __launch_bounds__(256, 2) void proj_out(const float* __restrict__ bias,
                                                   float* __restrict__ out)
{
    proj_body(g_oh, g_wh + 3 * (size_t)WSZ, bias, out, nullptr, nullptr, nullptr, 0.f);
}

// ---------------------------------------------------------------------------
// Flash attention (fp16, 1-term): 128-query tiles, 256 thr. Scores in log2
// domain (Q carries log2e); mask as PRE-CONVERTED fp16 additive bias applied
// with packed hadd2 after pk2h; softmax via ex2.approx.f16x2 (output IS the
// PV A-fragment); l accumulated in half2. 3-stage cp.async KV pipeline.
// smem: Q 18432 + 3 x {K,V} 18432 + 3 x bias 128 = 74112 B.
// ---------------------------------------------------------------------------
__global__ __launch_bounds__(256, 2) void attn_mma(const float* __restrict__ mask)
{
    extern __shared__ __align__(16) char smraw[];
    const unsigned smb = sa(smraw);
    const unsigned QH = 0, KV = 18432u, MK = 73728u;

    const int b   = blockIdx.z;
    const int h   = blockIdx.y;
    const int t0  = blockIdx.x * 128;
    const int tid = threadIdx.x;
    const int lane = tid & 31;
    const int w    = tid >> 5;

    // ---- Q load (fp16), shares cp.async group 0 with KV stage 0 ----
#pragma unroll
    for (int i = 0; i < 4; i++) {
        int idx = tid + i * 256;
        int r = idx >> 3, c = idx & 7;
        size_t gi = (size_t)(b * TT + t0 + r) * EMB + h * DD + c * 8;
        CP_ASYNC16(smb + QH + r * 144 + c * 16, g_qh + gi);
    }

    auto load_kv = [&](int s, int kt) {
        const unsigned base = smb + KV + (unsigned)s * 18432u;
        const int s0 = kt * 64;
#pragma unroll
        for (int i = 0; i < 2; i++) {
            int idx = tid + i * 256;
            int r = idx >> 3, c = idx & 7;
            size_t gi = (size_t)(b * TT + s0 + r) * EMB + h * DD + c * 8;
            unsigned d = base + r * 144 + c * 16;
            CP_ASYNC16(d,         g_kh + gi);
            CP_ASYNC16(d + 9216u, g_vh + gi);
        }
        if (tid < 8)
            CP_ASYNC16(smb + MK + (unsigned)s * 128u + tid * 16,
                       g_mb + b * TT + s0 + tid * 8);
    };

    load_kv(0, 0); CP_COMMIT();
    load_kv(1, 1); CP_COMMIT();

    const unsigned qh_a = smb + QH + (w * 16 + (lane & 15)) * 144 + (lane >> 4) * 16;
    const unsigned koff = (((lane >> 4) << 3) + (lane & 7)) * 144 + ((lane >> 3) & 1) * 16;
    const unsigned voff = ((((lane >> 3) & 1) * 8 + (lane & 7)) * 72 + ((lane >> 4) << 3)) * 2;

    // ---- wait Q (+stage0), hoist Q fragments into registers ----
    CP_WAIT(1);
    __syncthreads();
    unsigned qhf[4][4];
#pragma unroll
    for (int kc = 0; kc < 4; kc++)
        ldsm4(qhf[kc], qh_a + kc * 32);

    float oa[8][4];
#pragma unroll
    for (int j = 0; j < 8; j++)
#pragma unroll
        for (int e = 0; e < 4; e++) oa[j][e] = 0.f;
    float l0 = 0.f, l1 = 0.f;

    const float rb0f = (mask[b * TT + t0 + w * 16 + (lane >> 2)]     > 0.f) ? 0.f : -100.f;
    const float rb1f = (mask[b * TT + t0 + w * 16 + (lane >> 2) + 8] > 0.f) ? 0.f : -100.f;
    const unsigned rb0 = pk2h(rb0f, rb0f);
    const unsigned rb1 = pk2h(rb1f, rb1f);

    for (int kt = 0; kt < TT / 64; kt++) {
        if (kt < TT / 64 - 1) { CP_WAIT(1); } else { CP_WAIT(0); }
        __syncthreads();
        if (kt + 2 < TT / 64) { load_kv((kt + 2) % 3, kt + 2); CP_COMMIT(); }

        const unsigned stb  = smb + KV + (unsigned)(kt % 3) * 18432u;
        const unsigned kh_a = stb + koff;
        const unsigned vh_a = stb + 9216u + voff;
        const unsigned* mkb =
            (const unsigned*)(smraw + MK + (unsigned)(kt % 3) * 128u);

        // ---- S (log2 domain) = Q * K ----
        float sc[8][4];
#pragma unroll
        for (int j = 0; j < 8; j++)
#pragma unroll
            for (int e = 0; e < 4; e++) sc[j][e] = 0.f;

#pragma unroll
        for (int kc = 0; kc < 4; kc++) {
#pragma unroll
            for (int jp = 0; jp < 4; jp++) {
                unsigned bh[4];
                ldsm4(bh, kh_a + kc * 32 + jp * 16 * 144);
                mma16816h(sc[2 * jp],     qhf[kc], bh[0], bh[1]);
                mma16816h(sc[2 * jp + 1], qhf[kc], bh[2], bh[3]);
            }
        }

        // ---- packed mask bias + ex2 -> P fragments; l in half2 ----
        unsigned p01[8], p23[8];
        __half2 lt0 = __floats2half2_rn(0.f, 0.f);
        __half2 lt1 = lt0;
#pragma unroll
        for (int j = 0; j < 8; j++) {
            unsigned cb = mkb[j * 4 + (lane & 3)];    // half2 col bias
            p01[j] = ex2h2(hadd2u(hadd2u(pk2h(sc[j][0], sc[j][1]), cb), rb0));
            p23[j] = ex2h2(hadd2u(hadd2u(pk2h(sc[j][2], sc[j][3]), cb), rb1));
            lt0 = __hadd2(lt0, *reinterpret_cast<__half2*>(&p01[j]));
            lt1 = __hadd2(lt1, *reinterpret_cast<__half2*>(&p23[j]));
        }
        {
            float2 f0 = __half22float2(lt0);
            float2 f1 = __half22float2(lt1);
            l0 += f0.x + f0.y;
            l1 += f1.x + f1.y;
        }

        // ---- O += P * V ----
#pragma unroll
        for (int kc = 0; kc < 4; kc++) {
            unsigned a[4];
            a[0] = p01[2 * kc];     a[1] = p23[2 * kc];
            a[2] = p01[2 * kc + 1]; a[3] = p23[2 * kc + 1];
#pragma unroll
            for (int jp = 0; jp < 4; jp++) {
                unsigned bv[4];
                ldsm4t(bv, vh_a + kc * 16 * 144 + jp * 32);
                mma16816h(oa[2 * jp],     a, bv[0], bv[1]);
                mma16816h(oa[2 * jp + 1], a, bv[2], bv[3]);
            }
        }
    }

    // ---- epilogue: reduce l across quad, O / l -> fp16 ----
    l0 += __shfl_xor_sync(0xffffffffu, l0, 1);
    l0 += __shfl_xor_sync(0xffffffffu, l0, 2);
    l1 += __shfl_xor_sync(0xffffffffu, l1, 1);
    l1 += __shfl_xor_sync(0xffffffffu, l1, 2);
    const float inv0 = 1.f / l0;
    const float inv1 = 1.f / l1;
    const int gr0 = b * TT + t0 + w * 16 + (lane >> 2);
#pragma unroll
    for (int j = 0; j < 8; j++) {
        const int col = h * DD + j * 8 + (lane & 3) * 2;
        *(unsigned*)&g_oh[(size_t)gr0 * EMB + col] =
            pk2h(oa[j][0] * inv0, oa[j][1] * inv0);
        *(unsigned*)&g_oh[(size_t)(gr0 + 8) * EMB + col] =
            pk2h(oa[j][2] * inv1, oa[j][3] * inv1);
    }
}

// ---------------------------------------------------------------------------
extern "C" void kernel_launch(void* const* d_in, const int* in_sizes, int n_in,
                              void* d_out, int out_size)
{
    const float* x    = (const float*)d_in[0];
    const float* mask = (const float*)d_in[1];
    const float* Wk   = (const float*)d_in[2];
    const float* Wq   = (const float*)d_in[3];
    const float* Wv   = (const float*)d_in[4];
    const float* Wu   = (const float*)d_in[5];
    const float* bu   = (const float*)d_in[6];
    const float* klng = (const float*)d_in[7];
    const float* klnb = (const float*)d_in[8];
    const float* qlng = (const float*)d_in[9];
    const float* qlnb = (const float*)d_in[10];
    float* out = (float*)d_out;

    const int SPLIT_ITEMS = (ME * EMB + 4 * WSZ + BB * TT) / 4;
    split_all<<<(SPLIT_ITEMS + 255) / 256, 256>>>(x, Wk, Wq, Wv, Wu, mask);

    const int PSMEM = 3 * 27648;  // 82944
    cudaFuncSetAttribute(proj_qkv,
                         cudaFuncAttributeMaxDynamicSharedMemorySize, PSMEM);
    cudaFuncSetAttribute(proj_out,
                         cudaFuncAttributeMaxDynamicSharedMemorySize, PSMEM);
    proj_qkv<<<dim3(ME / 128, EMB / 64, 3), 256, PSMEM>>>(klng, klnb, qlng, qlnb);

    const int ASMEM = 18432 + 3 * 18432 + 3 * 128;  // 74112
    cudaFuncSetAttribute(attn_mma,
                         cudaFuncAttributeMaxDynamicSharedMemorySize, ASMEM);
    attn_mma<<<dim3(TT / 128, HH, BB), 256, ASMEM>>>(mask);

    proj_out<<<dim3(ME / 128, EMB / 64, 1), 256, PSMEM>>>(bu, out);
}